// round 6
// baseline (speedup 1.0000x reference)
#include <cuda_runtime.h>
#include <cstdint>

#define BATCH   4
#define SEQ     4096
#define HID     2048
#define NHEADS  16
#define HDIM    128
#define MTOT    (BATCH*SEQ)   /* 16384 */
#define NQKV    (3*HID)       /* 6144  */

// ---------------- scratch (device globals; no runtime alloc) ----------------
__device__ float g_xr [(size_t)MTOT*HID];    // tf32-rounded x
__device__ float g_qkv[(size_t)MTOT*NQKV];   // qkv rows
__device__ float g_ctx[(size_t)MTOT*HID];    // permuted context (tf32-rounded)
__device__ float g_WT1[(size_t)NQKV*HID];    // Wqkv^T  [6144][2048], tf32-rounded
__device__ float g_WT2[(size_t)HID*HID];     // Wproj^T [2048][2048], tf32-rounded

// ---------------- helpers ----------------
__device__ __forceinline__ float tf32r(float x){
    unsigned u; asm("cvt.rna.tf32.f32 %0, %1;" : "=r"(u) : "f"(x));
    return __uint_as_float(u);
}
__device__ __forceinline__ uint32_t smem_u32(const void* p){
    uint32_t a;
    asm("{ .reg .u64 t; cvta.to.shared.u64 t, %1; cvt.u32.u64 %0, t; }"
        : "=r"(a) : "l"(p));
    return a;
}
__device__ __forceinline__ void cp_async16(uint32_t dst, const void* src){
    asm volatile("cp.async.cg.shared.global [%0], [%1], 16;"
                 :: "r"(dst), "l"(src));
}
#define LDSM4(rr, addr) \
    asm volatile("ldmatrix.sync.aligned.m8n8.x4.shared.b16 {%0,%1,%2,%3}, [%4];" \
        : "=r"((rr)[0]),"=r"((rr)[1]),"=r"((rr)[2]),"=r"((rr)[3]) : "r"(addr))

__device__ __forceinline__ void mma8u(float* c, const uint32_t* a,
                                      uint32_t b0, uint32_t b1){
    asm volatile("mma.sync.aligned.m16n8k8.row.col.f32.tf32.tf32.f32 "
        "{%0,%1,%2,%3},{%4,%5,%6,%7},{%8,%9},{%0,%1,%2,%3};"
        : "+f"(c[0]),"+f"(c[1]),"+f"(c[2]),"+f"(c[3])
        : "r"(a[0]),"r"(a[1]),"r"(a[2]),"r"(a[3]), "r"(b0),"r"(b1));
}

// ---------------------------------------------------------------------------
// TF32 mma.sync GEMM, ldmatrix feed + cp.async pipeline.
// C[M x N] = A[M x K] * BT[N x K]^T + bias.
// CTA: 512 threads (16 warps, 2x8), tile 128 x 256, warp tile 64x32.
// KC=32, 4 stages. A and BT must be pre-rounded to tf32.
// ---------------------------------------------------------------------------
#define ROWB      144                 /* bytes per smem row (36 floats) */
#define STG_BYTES (384*ROWB)          /* 55296: 128 A-rows + 256 B-rows */
#define STAGES    4

__global__ void __launch_bounds__(512, 1)
tc_gemm(const float* __restrict__ A, const float* __restrict__ BT,
        const float* __restrict__ bias, float* __restrict__ C,
        int K, int N)
{
    extern __shared__ char dsm[];
    const uint32_t smem = smem_u32(dsm);
    const int tid = threadIdx.x, warp = tid>>5, lane = tid&31;
    const int g = lane>>2, t = lane&3;
    const int wm = warp>>3, wn = warp&7;             // 2 x 8 warps, 64x32 each
    const int m0 = blockIdx.y*128, n0 = blockIdx.x*256;
    const int NCH = K/32;

    const float* Ab = A  + (size_t)m0*K;
    const float* Bb = BT + (size_t)n0*K;

    // ldmatrix per-lane base offsets
    const int m8 = lane>>3, r8 = lane&7;
    const uint32_t aoff = (uint32_t)((wm*64 + (m8&1)*8 + r8)*ROWB + (m8>>1)*16);
    const uint32_t boff = (uint32_t)(128*ROWB
                        + (wn*32 + (m8>>1)*8 + r8)*ROWB + (m8&1)*16);

    float acc[4][4][4];
    #pragma unroll
    for(int i=0;i<4;++i)
        #pragma unroll
        for(int j=0;j<4;++j)
            #pragma unroll
            for(int e=0;e<4;++e) acc[i][j][e]=0.f;

    auto load_chunk = [&](int c, int s){
        const uint32_t base = smem + s*STG_BYTES;
        const float* Ag = Ab + c*32;
        const float* Bg = Bb + c*32;
        #pragma unroll
        for(int i=0;i<2;++i){                        // A: 128 rows x 8 segs
            int seg = tid + 512*i;
            int r = seg>>3, sc = (seg&7)<<4;
            cp_async16(base + r*ROWB + sc, (const char*)(Ag + (size_t)r*K) + sc);
        }
        #pragma unroll
        for(int i=0;i<4;++i){                        // B: 256 rows x 8 segs
            int seg = tid + 512*i;
            int r = seg>>3, sc = (seg&7)<<4;
            cp_async16(base + 128*ROWB + r*ROWB + sc,
                       (const char*)(Bg + (size_t)r*K) + sc);
        }
        asm volatile("cp.async.commit_group;" ::: "memory");
    };

    load_chunk(0,0); load_chunk(1,1); load_chunk(2,2); load_chunk(3,3);

    int s = 0;
    for(int c=0;c<NCH;++c){
        int rem = NCH-1-c; if (rem > 3) rem = 3;
        switch(rem){
            case 3:  asm volatile("cp.async.wait_group 3;" ::: "memory"); break;
            case 2:  asm volatile("cp.async.wait_group 2;" ::: "memory"); break;
            case 1:  asm volatile("cp.async.wait_group 1;" ::: "memory"); break;
            default: asm volatile("cp.async.wait_group 0;" ::: "memory"); break;
        }
        __syncthreads();

        const uint32_t aA = smem + s*STG_BYTES + aoff;
        const uint32_t bA = smem + s*STG_BYTES + boff;
        #pragma unroll
        for(int ks=0; ks<4; ++ks){
            uint32_t af[4][4], bf[2][4];
            #pragma unroll
            for(int i=0;i<4;++i)  LDSM4(af[i], aA + i*(16*ROWB) + ks*32);
            #pragma unroll
            for(int jp=0;jp<2;++jp) LDSM4(bf[jp], bA + jp*(16*ROWB) + ks*32);
            #pragma unroll
            for(int i=0;i<4;++i){
                mma8u(acc[i][0], af[i], bf[0][0], bf[0][1]);
                mma8u(acc[i][1], af[i], bf[0][2], bf[0][3]);
                mma8u(acc[i][2], af[i], bf[1][0], bf[1][1]);
                mma8u(acc[i][3], af[i], bf[1][2], bf[1][3]);
            }
        }
        __syncthreads();
        if (c+4 < NCH) load_chunk(c+4, s);
        s = (s==STAGES-1) ? 0 : s+1;
    }

    // epilogue: direct float2 stores + bias
    #pragma unroll
    for(int i=0;i<4;++i){
        #pragma unroll
        for(int j=0;j<4;++j){
            int r0 = m0 + wm*64 + i*16 + g;
            int c0 = n0 + wn*32 + j*8 + 2*t;
            float2 b01 = make_float2(bias[c0], bias[c0+1]);
            float2 v0 = make_float2(acc[i][j][0]+b01.x, acc[i][j][1]+b01.y);
            float2 v1 = make_float2(acc[i][j][2]+b01.x, acc[i][j][3]+b01.y);
            *(float2*)(C + (size_t)r0*N + c0)     = v0;
            *(float2*)(C + (size_t)(r0+8)*N + c0) = v1;
        }
    }
}

// ---------------------------------------------------------------------------
// prepass: round x to tf32 (rna)
// ---------------------------------------------------------------------------
__global__ void __launch_bounds__(1024)
round_kernel(const float* __restrict__ x, float* __restrict__ y, int n4)
{
    int i = blockIdx.x*blockDim.x + threadIdx.x;
    if (i < n4){
        float4 v = ((const float4*)x)[i];
        v.x=tf32r(v.x); v.y=tf32r(v.y); v.z=tf32r(v.z); v.w=tf32r(v.w);
        ((float4*)y)[i] = v;
    }
}

// ---------------------------------------------------------------------------
// prepass: transpose + round. W[K][N] -> WT[N][K]
// ---------------------------------------------------------------------------
__global__ void __launch_bounds__(256)
transpose_kernel(const float* __restrict__ W, float* __restrict__ WT,
                 int K, int N)
{
    __shared__ float tbuf[32][33];
    const int n0 = blockIdx.x*32, k0 = blockIdx.y*32;
    const int tx = threadIdx.x & 31, ty = threadIdx.x >> 5;  // 32 x 8
    #pragma unroll
    for(int i=0;i<4;++i)
        tbuf[ty+8*i][tx] = W[(size_t)(k0+ty+8*i)*N + n0+tx];
    __syncthreads();
    #pragma unroll
    for(int i=0;i<4;++i)
        WT[(size_t)(n0+ty+8*i)*K + k0+tx] = tf32r(tbuf[tx][ty+8*i]);
}

// ---------------------------------------------------------------------------
// Per-position head-mixing attention (reference einsum semantics).
// Writes g_ctx tf32-rounded, in transpose(0,2,1,3).reshape layout.
// ---------------------------------------------------------------------------
__global__ void __launch_bounds__(128)
attn_kernel()
{
    __shared__ float S[48*132];

    const int tid = threadIdx.x;
    const size_t pos = blockIdx.x;               // b*4096 + s
    const float* row = g_qkv + pos*NQKV;

    #pragma unroll
    for(int it=0; it<12; ++it){
        int idx = tid + 128*it;
        int f = idx<<2;
        int r = f>>7, c = f&127;
        *(float4*)(S + r*132 + c) = *(const float4*)(row + f);
    }
    __syncthreads();

    const int h = tid>>3, i = tid&7;
    const float4* Q4 = (const float4*)(S + h*132);
    const float4* K0 = (const float4*)(S + (16+i)*132);
    const float4* K1 = (const float4*)(S + (24+i)*132);

    float s0=0.f, s1=0.f;
    #pragma unroll
    for(int d=0; d<32; ++d){
        float4 q = Q4[d], a = K0[d], b = K1[d];
        s0 += q.x*a.x + q.y*a.y + q.z*a.z + q.w*a.w;
        s1 += q.x*b.x + q.y*b.y + q.z*b.z + q.w*b.w;
    }
    const float sc = 0.08838834764831845f;       // 1/sqrt(128)
    s0 *= sc; s1 *= sc;

    float m = fmaxf(s0, s1);
    m = fmaxf(m, __shfl_xor_sync(0xffffffffu, m, 1));
    m = fmaxf(m, __shfl_xor_sync(0xffffffffu, m, 2));
    m = fmaxf(m, __shfl_xor_sync(0xffffffffu, m, 4));
    float e0 = __expf(s0 - m), e1 = __expf(s1 - m);
    float sum = e0 + e1;
    sum += __shfl_xor_sync(0xffffffffu, sum, 1);
    sum += __shfl_xor_sync(0xffffffffu, sum, 2);
    sum += __shfl_xor_sync(0xffffffffu, sum, 4);
    float inv = 1.f/sum;
    float w0 = e0*inv, w1 = e1*inv;

    float wv[16];
    #pragma unroll
    for(int j=0;j<8;++j){
        wv[j]   = __shfl_sync(0xffffffffu, w0, j, 8);
        wv[j+8] = __shfl_sync(0xffffffffu, w1, j, 8);
    }

    const int b = (int)(pos>>12), s = (int)(pos&4095);
    float* orow = g_ctx + ((size_t)(b*SEQ + h*256 + (s>>4)))*HID + (size_t)(s&15)*HDIM;
    #pragma unroll
    for(int j=0;j<4;++j){
        int d4 = i + 8*j;
        float4 acc = make_float4(0.f,0.f,0.f,0.f);
        #pragma unroll
        for(int tt=0;tt<16;++tt){
            float4 v = *(const float4*)(S + (32+tt)*132 + (d4<<2));
            acc.x += wv[tt]*v.x; acc.y += wv[tt]*v.y;
            acc.z += wv[tt]*v.z; acc.w += wv[tt]*v.w;
        }
        acc.x=tf32r(acc.x); acc.y=tf32r(acc.y);
        acc.z=tf32r(acc.z); acc.w=tf32r(acc.w);
        *(float4*)(orow + (d4<<2)) = acc;
    }
}

// ---------------------------------------------------------------------------
extern "C" void kernel_launch(void* const* d_in, const int* in_sizes, int n_in,
                              void* d_out, int out_size)
{
    const float* x     = (const float*)d_in[0];
    const float* Wqkv  = (const float*)d_in[1];
    const float* bqkv  = (const float*)d_in[2];
    const float* Wproj = (const float*)d_in[3];
    const float* bproj = (const float*)d_in[4];
    float* out = (float*)d_out;

    cudaFuncSetAttribute(tc_gemm, cudaFuncAttributeMaxDynamicSharedMemorySize,
                         STAGES*STG_BYTES);

    float *xr, *qkv, *ctx, *wt1, *wt2;
    cudaGetSymbolAddress((void**)&xr,  g_xr);
    cudaGetSymbolAddress((void**)&qkv, g_qkv);
    cudaGetSymbolAddress((void**)&ctx, g_ctx);
    cudaGetSymbolAddress((void**)&wt1, g_WT1);
    cudaGetSymbolAddress((void**)&wt2, g_WT2);

    const int n4 = MTOT*HID/4;
    round_kernel<<<(n4+1023)/1024, 1024>>>(x, xr, n4);
    transpose_kernel<<<dim3(NQKV/32, HID/32), 256>>>(Wqkv, wt1, HID, NQKV);
    transpose_kernel<<<dim3(HID/32,  HID/32), 256>>>(Wproj, wt2, HID, HID);

    tc_gemm<<<dim3(NQKV/256, MTOT/128), 512, STAGES*STG_BYTES>>>(
        xr, wt1, bqkv, qkv, HID, NQKV);
    attn_kernel<<<MTOT, 128>>>();
    tc_gemm<<<dim3(HID/256, MTOT/128), 512, STAGES*STG_BYTES>>>(
        ctx, wt2, bproj, out, HID, HID);
}

// round 7
// speedup vs baseline: 1.1429x; 1.1429x over previous
#include <cuda_runtime.h>
#include <cstdint>

#define BATCH   4
#define SEQ     4096
#define HID     2048
#define NHEADS  16
#define HDIM    128
#define MTOT    (BATCH*SEQ)   /* 16384 */
#define NQKV    (3*HID)       /* 6144  */

// ---------------- scratch (device globals; no runtime alloc) ----------------
__device__ float g_xr [(size_t)MTOT*HID];    // tf32-rounded x
__device__ float g_qkv[(size_t)MTOT*NQKV];   // qkv rows
__device__ float g_ctx[(size_t)MTOT*HID];    // permuted context (tf32-rounded)
__device__ float g_WT1[(size_t)NQKV*HID];    // Wqkv^T  [6144][2048], tf32-rounded
__device__ float g_WT2[(size_t)HID*HID];     // Wproj^T [2048][2048], tf32-rounded

// ---------------- helpers ----------------
__device__ __forceinline__ float tf32r(float x){
    unsigned u; asm("cvt.rna.tf32.f32 %0, %1;" : "=r"(u) : "f"(x));
    return __uint_as_float(u);
}
__device__ __forceinline__ uint32_t smem_u32(const void* p){
    uint32_t a;
    asm("{ .reg .u64 t; cvta.to.shared.u64 t, %1; cvt.u32.u64 %0, t; }"
        : "=r"(a) : "l"(p));
    return a;
}
__device__ __forceinline__ void cp_async16(uint32_t dst, const void* src){
    asm volatile("cp.async.cg.shared.global [%0], [%1], 16;"
                 :: "r"(dst), "l"(src));
}
#define LDSM4(rr, addr) \
    asm volatile("ldmatrix.sync.aligned.m8n8.x4.shared.b16 {%0,%1,%2,%3}, [%4];" \
        : "=r"((rr)[0]),"=r"((rr)[1]),"=r"((rr)[2]),"=r"((rr)[3]) : "r"(addr))

__device__ __forceinline__ void mma8u(float* c, const uint32_t* a,
                                      uint32_t b0, uint32_t b1){
    asm volatile("mma.sync.aligned.m16n8k8.row.col.f32.tf32.tf32.f32 "
        "{%0,%1,%2,%3},{%4,%5,%6,%7},{%8,%9},{%0,%1,%2,%3};"
        : "+f"(c[0]),"+f"(c[1]),"+f"(c[2]),"+f"(c[3])
        : "r"(a[0]),"r"(a[1]),"r"(a[2]),"r"(a[3]), "r"(b0),"r"(b1));
}

// ---------------------------------------------------------------------------
// TF32 mma.sync GEMM, ldmatrix feed + cp.async pipeline.
// C[M x N] = A[M x K] * BT[N x K]^T + bias. CTA tile 128x128 (8 warps, 64x32
// warp tile), KC=32, 3 stages, 2 CTAs/SM, ONE barrier per K-chunk.
// A and BT must be pre-rounded to tf32.
// ---------------------------------------------------------------------------
#define ROWB      144                 /* bytes per smem row (36 floats) */
#define STG_BYTES (256*ROWB)          /* 36864: 128 A-rows + 128 B-rows */
#define STAGES    3

__global__ void __launch_bounds__(256, 2)
tc_gemm(const float* __restrict__ A, const float* __restrict__ BT,
        const float* __restrict__ bias, float* __restrict__ C,
        int K, int N)
{
    extern __shared__ char dsm[];
    const uint32_t smem = smem_u32(dsm);
    const int tid = threadIdx.x, warp = tid>>5, lane = tid&31;
    const int g = lane>>2, t = lane&3;
    const int wm = warp>>2, wn = warp&3;             // 2 x 4 warps, 64x32 each
    const int m0 = blockIdx.y*128, n0 = blockIdx.x*128;
    const int NCH = K/32;

    const float* Ab = A  + (size_t)m0*K;
    const float* Bb = BT + (size_t)n0*K;

    // ldmatrix per-lane base offsets (4 matrices per x4)
    const int m8 = lane>>3, r8 = lane&7;
    const uint32_t aoff = (uint32_t)((wm*64 + (m8&1)*8 + r8)*ROWB + (m8>>1)*16);
    const uint32_t boff = (uint32_t)(128*ROWB + (wn*32 + (m8>>1)*8 + r8)*ROWB + (m8&1)*16);

    float acc[4][4][4];
    #pragma unroll
    for(int i=0;i<4;++i)
        #pragma unroll
        for(int j=0;j<4;++j)
            #pragma unroll
            for(int e=0;e<4;++e) acc[i][j][e]=0.f;

    auto load_chunk = [&](int c, int s){
        const uint32_t base = smem + s*STG_BYTES;
        const float* Ag = Ab + c*32;
        const float* Bg = Bb + c*32;
        #pragma unroll
        for(int i=0;i<4;++i){
            int seg = tid + 256*i;                   // A: 128 rows x 8 segs
            int r = seg>>3, sc = (seg&7)<<4;
            cp_async16(base + r*ROWB + sc, (const char*)(Ag + (size_t)r*K) + sc);
        }
        #pragma unroll
        for(int i=0;i<4;++i){
            int seg = tid + 256*i;                   // B: 128 rows x 8 segs
            int r = seg>>3, sc = (seg&7)<<4;
            cp_async16(base + 128*ROWB + r*ROWB + sc,
                       (const char*)(Bg + (size_t)r*K) + sc);
        }
        asm volatile("cp.async.commit_group;" ::: "memory");
    };

    // prefetch chunks 0 and 1
    load_chunk(0,0); load_chunk(1,1);

    int s = 0;                                       // stage of chunk c
    for(int c=0;c<NCH;++c){
        if (c+1 < NCH) asm volatile("cp.async.wait_group 1;" ::: "memory");
        else           asm volatile("cp.async.wait_group 0;" ::: "memory");
        __syncthreads();
        // issue next load BEFORE the MMA block (overwrites stage (c-1)%3,
        // which the barrier above proved is no longer being read)
        if (c+2 < NCH){
            int s2 = s+2; if (s2 >= STAGES) s2 -= STAGES;
            load_chunk(c+2, s2);
        }

        const uint32_t aA = smem + s*STG_BYTES + aoff;
        const uint32_t bA = smem + s*STG_BYTES + boff;
        #pragma unroll
        for(int ks=0; ks<4; ++ks){
            uint32_t af[4][4], bf[2][4];
            #pragma unroll
            for(int i=0;i<4;++i) LDSM4(af[i], aA + i*(16*ROWB) + ks*32);
            #pragma unroll
            for(int jp=0;jp<2;++jp) LDSM4(bf[jp], bA + jp*(16*ROWB) + ks*32);
            #pragma unroll
            for(int i=0;i<4;++i){
                mma8u(acc[i][0], af[i], bf[0][0], bf[0][1]);
                mma8u(acc[i][1], af[i], bf[0][2], bf[0][3]);
                mma8u(acc[i][2], af[i], bf[1][0], bf[1][1]);
                mma8u(acc[i][3], af[i], bf[1][2], bf[1][3]);
            }
        }
        s = (s==STAGES-1) ? 0 : s+1;
    }

    // epilogue: direct float2 stores + bias
    #pragma unroll
    for(int i=0;i<4;++i){
        #pragma unroll
        for(int j=0;j<4;++j){
            int r0 = m0 + wm*64 + i*16 + g;
            int c0 = n0 + wn*32 + j*8 + 2*t;
            float2 b01 = make_float2(bias[c0], bias[c0+1]);
            float2 v0 = make_float2(acc[i][j][0]+b01.x, acc[i][j][1]+b01.y);
            float2 v1 = make_float2(acc[i][j][2]+b01.x, acc[i][j][3]+b01.y);
            *(float2*)(C + (size_t)r0*N + c0)     = v0;
            *(float2*)(C + (size_t)(r0+8)*N + c0) = v1;
        }
    }
}

// ---------------------------------------------------------------------------
// prepass: round x to tf32 (rna)
// ---------------------------------------------------------------------------
__global__ void __launch_bounds__(1024)
round_kernel(const float* __restrict__ x, float* __restrict__ y, int n4)
{
    int i = blockIdx.x*blockDim.x + threadIdx.x;
    if (i < n4){
        float4 v = ((const float4*)x)[i];
        v.x=tf32r(v.x); v.y=tf32r(v.y); v.z=tf32r(v.z); v.w=tf32r(v.w);
        ((float4*)y)[i] = v;
    }
}

// ---------------------------------------------------------------------------
// prepass: transpose + round. W[K][N] -> WT[N][K]
// ---------------------------------------------------------------------------
__global__ void __launch_bounds__(256)
transpose_kernel(const float* __restrict__ W, float* __restrict__ WT,
                 int K, int N)
{
    __shared__ float tbuf[32][33];
    const int n0 = blockIdx.x*32, k0 = blockIdx.y*32;
    const int tx = threadIdx.x & 31, ty = threadIdx.x >> 5;  // 32 x 8
    #pragma unroll
    for(int i=0;i<4;++i)
        tbuf[ty+8*i][tx] = W[(size_t)(k0+ty+8*i)*N + n0+tx];
    __syncthreads();
    #pragma unroll
    for(int i=0;i<4;++i)
        WT[(size_t)(n0+ty+8*i)*K + k0+tx] = tf32r(tbuf[tx][ty+8*i]);
}

// ---------------------------------------------------------------------------
// Per-position head-mixing attention (reference einsum semantics).
// Writes g_ctx tf32-rounded, in transpose(0,2,1,3).reshape layout.
// ---------------------------------------------------------------------------
__global__ void __launch_bounds__(128)
attn_kernel()
{
    __shared__ float S[48*132];

    const int tid = threadIdx.x;
    const size_t pos = blockIdx.x;               // b*4096 + s
    const float* row = g_qkv + pos*NQKV;

    #pragma unroll
    for(int it=0; it<12; ++it){
        int idx = tid + 128*it;
        int f = idx<<2;
        int r = f>>7, c = f&127;
        *(float4*)(S + r*132 + c) = *(const float4*)(row + f);
    }
    __syncthreads();

    const int h = tid>>3, i = tid&7;
    const float4* Q4 = (const float4*)(S + h*132);
    const float4* K0 = (const float4*)(S + (16+i)*132);
    const float4* K1 = (const float4*)(S + (24+i)*132);

    float s0=0.f, s1=0.f;
    #pragma unroll
    for(int d=0; d<32; ++d){
        float4 q = Q4[d], a = K0[d], b = K1[d];
        s0 += q.x*a.x + q.y*a.y + q.z*a.z + q.w*a.w;
        s1 += q.x*b.x + q.y*b.y + q.z*b.z + q.w*b.w;
    }
    const float sc = 0.08838834764831845f;       // 1/sqrt(128)
    s0 *= sc; s1 *= sc;

    float m = fmaxf(s0, s1);
    m = fmaxf(m, __shfl_xor_sync(0xffffffffu, m, 1));
    m = fmaxf(m, __shfl_xor_sync(0xffffffffu, m, 2));
    m = fmaxf(m, __shfl_xor_sync(0xffffffffu, m, 4));
    float e0 = __expf(s0 - m), e1 = __expf(s1 - m);
    float sum = e0 + e1;
    sum += __shfl_xor_sync(0xffffffffu, sum, 1);
    sum += __shfl_xor_sync(0xffffffffu, sum, 2);
    sum += __shfl_xor_sync(0xffffffffu, sum, 4);
    float inv = 1.f/sum;
    float w0 = e0*inv, w1 = e1*inv;

    float wv[16];
    #pragma unroll
    for(int j=0;j<8;++j){
        wv[j]   = __shfl_sync(0xffffffffu, w0, j, 8);
        wv[j+8] = __shfl_sync(0xffffffffu, w1, j, 8);
    }

    const int b = (int)(pos>>12), s = (int)(pos&4095);
    float* orow = g_ctx + ((size_t)(b*SEQ + h*256 + (s>>4)))*HID + (size_t)(s&15)*HDIM;
    #pragma unroll
    for(int j=0;j<4;++j){
        int d4 = i + 8*j;
        float4 acc = make_float4(0.f,0.f,0.f,0.f);
        #pragma unroll
        for(int tt=0;tt<16;++tt){
            float4 v = *(const float4*)(S + (32+tt)*132 + (d4<<2));
            acc.x += wv[tt]*v.x; acc.y += wv[tt]*v.y;
            acc.z += wv[tt]*v.z; acc.w += wv[tt]*v.w;
        }
        acc.x=tf32r(acc.x); acc.y=tf32r(acc.y);
        acc.z=tf32r(acc.z); acc.w=tf32r(acc.w);
        *(float4*)(orow + (d4<<2)) = acc;
    }
}

// ---------------------------------------------------------------------------
extern "C" void kernel_launch(void* const* d_in, const int* in_sizes, int n_in,
                              void* d_out, int out_size)
{
    const float* x     = (const float*)d_in[0];
    const float* Wqkv  = (const float*)d_in[1];
    const float* bqkv  = (const float*)d_in[2];
    const float* Wproj = (const float*)d_in[3];
    const float* bproj = (const float*)d_in[4];
    float* out = (float*)d_out;

    cudaFuncSetAttribute(tc_gemm, cudaFuncAttributeMaxDynamicSharedMemorySize,
                         STAGES*STG_BYTES);

    float *xr, *qkv, *ctx, *wt1, *wt2;
    cudaGetSymbolAddress((void**)&xr,  g_xr);
    cudaGetSymbolAddress((void**)&qkv, g_qkv);
    cudaGetSymbolAddress((void**)&ctx, g_ctx);
    cudaGetSymbolAddress((void**)&wt1, g_WT1);
    cudaGetSymbolAddress((void**)&wt2, g_WT2);

    const int n4 = MTOT*HID/4;
    round_kernel<<<(n4+1023)/1024, 1024>>>(x, xr, n4);
    transpose_kernel<<<dim3(NQKV/32, HID/32), 256>>>(Wqkv, wt1, HID, NQKV);
    transpose_kernel<<<dim3(HID/32,  HID/32), 256>>>(Wproj, wt2, HID, HID);

    tc_gemm<<<dim3(NQKV/128, MTOT/128), 256, STAGES*STG_BYTES>>>(
        xr, wt1, bqkv, qkv, HID, NQKV);
    attn_kernel<<<MTOT, 128>>>();
    tc_gemm<<<dim3(HID/128, MTOT/128), 256, STAGES*STG_BYTES>>>(
        ctx, wt2, bproj, out, HID, HID);
}

// round 8
// speedup vs baseline: 2.0676x; 1.8091x over previous
#include <cuda_runtime.h>
#include <cuda_fp16.h>
#include <cstdint>

#define BATCH   4
#define SEQ     4096
#define HID     2048
#define NHEADS  16
#define HDIM    128
#define MTOT    (BATCH*SEQ)   /* 16384 */
#define NQKV    (3*HID)       /* 6144  */

// ---------------- scratch (device globals; no runtime alloc) ----------------
__device__ __half g_xh [(size_t)MTOT*HID];    // fp16 x
__device__ float  g_qkv[(size_t)MTOT*NQKV];   // qkv rows (fp32)
__device__ __half g_cth[(size_t)MTOT*HID];    // permuted context (fp16)
__device__ __half g_WT1[(size_t)NQKV*HID];    // Wqkv^T  [6144][2048] fp16
__device__ __half g_WT2[(size_t)HID*HID];     // Wproj^T [2048][2048] fp16

// ---------------- helpers ----------------
__device__ __forceinline__ uint32_t smem_u32(const void* p){
    uint32_t a;
    asm("{ .reg .u64 t; cvta.to.shared.u64 t, %1; cvt.u32.u64 %0, t; }"
        : "=r"(a) : "l"(p));
    return a;
}
__device__ __forceinline__ void cp_async16(uint32_t dst, const void* src){
    asm volatile("cp.async.cg.shared.global [%0], [%1], 16;"
                 :: "r"(dst), "l"(src));
}
#define LDSM4(rr, addr) \
    asm volatile("ldmatrix.sync.aligned.m8n8.x4.shared.b16 {%0,%1,%2,%3}, [%4];" \
        : "=r"((rr)[0]),"=r"((rr)[1]),"=r"((rr)[2]),"=r"((rr)[3]) : "r"(addr))

__device__ __forceinline__ void mma16(float* c, const uint32_t* a,
                                      uint32_t b0, uint32_t b1){
    asm volatile("mma.sync.aligned.m16n8k16.row.col.f32.f16.f16.f32 "
        "{%0,%1,%2,%3},{%4,%5,%6,%7},{%8,%9},{%0,%1,%2,%3};"
        : "+f"(c[0]),"+f"(c[1]),"+f"(c[2]),"+f"(c[3])
        : "r"(a[0]),"r"(a[1]),"r"(a[2]),"r"(a[3]), "r"(b0),"r"(b1));
}

// ---------------------------------------------------------------------------
// FP16 mma.sync GEMM (fp32 accumulate), ldmatrix feed + cp.async pipeline.
// C[M x N] = A[M x K] * BT[N x K]^T + bias. CTA tile 128x128 (8 warps, 64x32
// warp tile), KC=64 halves (128B/row), 3 stages, 2 CTAs/SM, 1 barrier/chunk.
// ---------------------------------------------------------------------------
#define ROWB      144                 /* bytes per smem row (64 halves + pad) */
#define STG_BYTES (256*ROWB)          /* 36864: 128 A-rows + 128 B-rows */
#define STAGES    3

__global__ void __launch_bounds__(256, 2)
hgemm(const __half* __restrict__ A, const __half* __restrict__ BT,
      const float* __restrict__ bias, float* __restrict__ C,
      int K, int N)
{
    extern __shared__ char dsm[];
    const uint32_t smem = smem_u32(dsm);
    const int tid = threadIdx.x, warp = tid>>5, lane = tid&31;
    const int g = lane>>2, t = lane&3;
    const int wm = warp>>2, wn = warp&3;             // 2 x 4 warps, 64x32 each
    const int m0 = blockIdx.y*128, n0 = blockIdx.x*128;
    const int NCH = K/64;

    const __half* Ab = A  + (size_t)m0*K;
    const __half* Bb = BT + (size_t)n0*K;

    // ldmatrix per-lane base offsets (4 8x8 b16 matrices per x4)
    const int m8 = lane>>3, r8 = lane&7;
    const uint32_t aoff = (uint32_t)((wm*64 + (m8&1)*8 + r8)*ROWB + (m8>>1)*16);
    const uint32_t boff = (uint32_t)(128*ROWB + (wn*32 + (m8>>1)*8 + r8)*ROWB + (m8&1)*16);

    float acc[4][4][4];
    #pragma unroll
    for(int i=0;i<4;++i)
        #pragma unroll
        for(int j=0;j<4;++j)
            #pragma unroll
            for(int e=0;e<4;++e) acc[i][j][e]=0.f;

    auto load_chunk = [&](int c, int s){
        const uint32_t base = smem + s*STG_BYTES;
        const __half* Ag = Ab + c*64;
        const __half* Bg = Bb + c*64;
        #pragma unroll
        for(int i=0;i<4;++i){
            int seg = tid + 256*i;                   // A: 128 rows x 8 x 16B
            int r = seg>>3, cb = (seg&7)<<4;
            cp_async16(base + r*ROWB + cb, (const char*)(Ag + (size_t)r*K) + cb);
        }
        #pragma unroll
        for(int i=0;i<4;++i){
            int seg = tid + 256*i;                   // B: 128 rows x 8 x 16B
            int r = seg>>3, cb = (seg&7)<<4;
            cp_async16(base + 128*ROWB + r*ROWB + cb,
                       (const char*)(Bg + (size_t)r*K) + cb);
        }
        asm volatile("cp.async.commit_group;" ::: "memory");
    };

    load_chunk(0,0); load_chunk(1,1);

    int s = 0;                                       // stage of chunk c
    for(int c=0;c<NCH;++c){
        if (c+1 < NCH) asm volatile("cp.async.wait_group 1;" ::: "memory");
        else           asm volatile("cp.async.wait_group 0;" ::: "memory");
        __syncthreads();
        if (c+2 < NCH){
            int s2 = s+2; if (s2 >= STAGES) s2 -= STAGES;
            load_chunk(c+2, s2);
        }

        const uint32_t aA = smem + s*STG_BYTES + aoff;
        const uint32_t bA = smem + s*STG_BYTES + boff;
        #pragma unroll
        for(int ks=0; ks<4; ++ks){                   // 4 K-steps of 16 halves
            uint32_t af[4][4], bf[2][4];
            #pragma unroll
            for(int i=0;i<4;++i) LDSM4(af[i], aA + i*(16*ROWB) + ks*32);
            #pragma unroll
            for(int jp=0;jp<2;++jp) LDSM4(bf[jp], bA + jp*(16*ROWB) + ks*32);
            #pragma unroll
            for(int i=0;i<4;++i){
                mma16(acc[i][0], af[i], bf[0][0], bf[0][1]);
                mma16(acc[i][1], af[i], bf[0][2], bf[0][3]);
                mma16(acc[i][2], af[i], bf[1][0], bf[1][1]);
                mma16(acc[i][3], af[i], bf[1][2], bf[1][3]);
            }
        }
        s = (s==STAGES-1) ? 0 : s+1;
    }

    // epilogue: direct float2 stores + bias
    #pragma unroll
    for(int i=0;i<4;++i){
        #pragma unroll
        for(int j=0;j<4;++j){
            int r0 = m0 + wm*64 + i*16 + g;
            int c0 = n0 + wn*32 + j*8 + 2*t;
            float2 b01 = make_float2(bias[c0], bias[c0+1]);
            float2 v0 = make_float2(acc[i][j][0]+b01.x, acc[i][j][1]+b01.y);
            float2 v1 = make_float2(acc[i][j][2]+b01.x, acc[i][j][3]+b01.y);
            *(float2*)(C + (size_t)r0*N + c0)     = v0;
            *(float2*)(C + (size_t)(r0+8)*N + c0) = v1;
        }
    }
}

// ---------------------------------------------------------------------------
// prepass: convert x fp32 -> fp16
// ---------------------------------------------------------------------------
__global__ void __launch_bounds__(1024)
tohalf_kernel(const float* __restrict__ x, __half* __restrict__ y, int n4)
{
    int i = blockIdx.x*blockDim.x + threadIdx.x;
    if (i < n4){
        float4 v = ((const float4*)x)[i];
        __half2 h0 = __floats2half2_rn(v.x, v.y);
        __half2 h1 = __floats2half2_rn(v.z, v.w);
        ((__half2*)y)[2*i]   = h0;
        ((__half2*)y)[2*i+1] = h1;
    }
}

// ---------------------------------------------------------------------------
// prepass: transpose + convert. W[K][N] fp32 -> WT[N][K] fp16
// ---------------------------------------------------------------------------
__global__ void __launch_bounds__(256)
transpose_kernel(const float* __restrict__ W, __half* __restrict__ WT,
                 int K, int N)
{
    __shared__ float tbuf[32][33];
    const int n0 = blockIdx.x*32, k0 = blockIdx.y*32;
    const int tx = threadIdx.x & 31, ty = threadIdx.x >> 5;  // 32 x 8
    #pragma unroll
    for(int i=0;i<4;++i)
        tbuf[ty+8*i][tx] = W[(size_t)(k0+ty+8*i)*N + n0+tx];
    __syncthreads();
    #pragma unroll
    for(int i=0;i<4;++i)
        WT[(size_t)(n0+ty+8*i)*K + k0+tx] = __float2half_rn(tbuf[tx][ty+8*i]);
}

// ---------------------------------------------------------------------------
// Per-position head-mixing attention (reference einsum semantics), fp32 math.
// Writes g_cth (fp16) in transpose(0,2,1,3).reshape layout.
// ---------------------------------------------------------------------------
__global__ void __launch_bounds__(128)
attn_kernel()
{
    __shared__ float S[48*132];

    const int tid = threadIdx.x;
    const size_t pos = blockIdx.x;               // b*4096 + s
    const float* row = g_qkv + pos*NQKV;

    #pragma unroll
    for(int it=0; it<12; ++it){
        int idx = tid + 128*it;
        int f = idx<<2;
        int r = f>>7, c = f&127;
        *(float4*)(S + r*132 + c) = *(const float4*)(row + f);
    }
    __syncthreads();

    const int h = tid>>3, i = tid&7;
    const float4* Q4 = (const float4*)(S + h*132);
    const float4* K0 = (const float4*)(S + (16+i)*132);
    const float4* K1 = (const float4*)(S + (24+i)*132);

    float s0=0.f, s1=0.f;
    #pragma unroll
    for(int d=0; d<32; ++d){
        float4 q = Q4[d], a = K0[d], b = K1[d];
        s0 += q.x*a.x + q.y*a.y + q.z*a.z + q.w*a.w;
        s1 += q.x*b.x + q.y*b.y + q.z*b.z + q.w*b.w;
    }
    const float sc = 0.08838834764831845f;       // 1/sqrt(128)
    s0 *= sc; s1 *= sc;

    float m = fmaxf(s0, s1);
    m = fmaxf(m, __shfl_xor_sync(0xffffffffu, m, 1));
    m = fmaxf(m, __shfl_xor_sync(0xffffffffu, m, 2));
    m = fmaxf(m, __shfl_xor_sync(0xffffffffu, m, 4));
    float e0 = __expf(s0 - m), e1 = __expf(s1 - m);
    float sum = e0 + e1;
    sum += __shfl_xor_sync(0xffffffffu, sum, 1);
    sum += __shfl_xor_sync(0xffffffffu, sum, 2);
    sum += __shfl_xor_sync(0xffffffffu, sum, 4);
    float inv = 1.f/sum;
    float w0 = e0*inv, w1 = e1*inv;

    float wv[16];
    #pragma unroll
    for(int j=0;j<8;++j){
        wv[j]   = __shfl_sync(0xffffffffu, w0, j, 8);
        wv[j+8] = __shfl_sync(0xffffffffu, w1, j, 8);
    }

    const int b = (int)(pos>>12), s = (int)(pos&4095);
    __half* orow = g_cth + ((size_t)(b*SEQ + h*256 + (s>>4)))*HID + (size_t)(s&15)*HDIM;
    #pragma unroll
    for(int j=0;j<4;++j){
        int d4 = i + 8*j;
        float4 acc = make_float4(0.f,0.f,0.f,0.f);
        #pragma unroll
        for(int tt=0;tt<16;++tt){
            float4 v = *(const float4*)(S + (32+tt)*132 + (d4<<2));
            acc.x += wv[tt]*v.x; acc.y += wv[tt]*v.y;
            acc.z += wv[tt]*v.z; acc.w += wv[tt]*v.w;
        }
        __half2 p0 = __floats2half2_rn(acc.x, acc.y);
        __half2 p1 = __floats2half2_rn(acc.z, acc.w);
        ((__half2*)(orow + (d4<<2)))[0] = p0;
        ((__half2*)(orow + (d4<<2)))[1] = p1;
    }
}

// ---------------------------------------------------------------------------
extern "C" void kernel_launch(void* const* d_in, const int* in_sizes, int n_in,
                              void* d_out, int out_size)
{
    const float* x     = (const float*)d_in[0];
    const float* Wqkv  = (const float*)d_in[1];
    const float* bqkv  = (const float*)d_in[2];
    const float* Wproj = (const float*)d_in[3];
    const float* bproj = (const float*)d_in[4];
    float* out = (float*)d_out;

    cudaFuncSetAttribute(hgemm, cudaFuncAttributeMaxDynamicSharedMemorySize,
                         STAGES*STG_BYTES);

    __half *xh, *cth, *wt1, *wt2;
    float *qkv;
    cudaGetSymbolAddress((void**)&xh,  g_xh);
    cudaGetSymbolAddress((void**)&qkv, g_qkv);
    cudaGetSymbolAddress((void**)&cth, g_cth);
    cudaGetSymbolAddress((void**)&wt1, g_WT1);
    cudaGetSymbolAddress((void**)&wt2, g_WT2);

    const int n4 = MTOT*HID/4;
    tohalf_kernel<<<(n4+1023)/1024, 1024>>>(x, xh, n4);
    transpose_kernel<<<dim3(NQKV/32, HID/32), 256>>>(Wqkv, wt1, HID, NQKV);
    transpose_kernel<<<dim3(HID/32,  HID/32), 256>>>(Wproj, wt2, HID, HID);

    hgemm<<<dim3(NQKV/128, MTOT/128), 256, STAGES*STG_BYTES>>>(
        xh, wt1, bqkv, qkv, HID, NQKV);
    attn_kernel<<<MTOT, 128>>>();
    hgemm<<<dim3(HID/128, MTOT/128), 256, STAGES*STG_BYTES>>>(
        cth, wt2, bproj, out, HID, HID);
}